// round 6
// baseline (speedup 1.0000x reference)
#include <cuda_runtime.h>

#define NS (1<<20)
#define GRID 148

// ---- device scratch (static, allocation-free) ----
__device__ float g_T0[NS];
__device__ float g_T1[NS];
__device__ float g_A[NS];      // T2 (pair*4096) early; then A[P01][bond] 1024x1024
__device__ float g_Cm[NS];     // Ct[P23][bond]  (1024x1024, transposed C)
__device__ float g_psi[NS];    // statevector (in-place for sweeps)
__device__ float g_R[1024];    // 32x32 row-chain operator [out][in]
__device__ float g_C16[256];   // 16x16 column-chain operator
__device__ float g_K[10*4096]; // per-column pair tensors K_j
__device__ float g_KK[2*65536];// combined column-pair operators KK23 per pair
__device__ unsigned g_bar = 0; // software grid barrier (self-resetting)
__device__ unsigned g_gen = 0;

// ---- packed fp32x2 helpers ----
__device__ __forceinline__ unsigned long long pk2(float x, float y){
    unsigned long long r; asm("mov.b64 %0,{%1,%2};" : "=l"(r) : "f"(x), "f"(y)); return r;
}
__device__ __forceinline__ float2 upk2(unsigned long long v){
    float2 r; asm("mov.b64 {%0,%1},%2;" : "=f"(r.x), "=f"(r.y) : "l"(v)); return r;
}
__device__ __forceinline__ unsigned long long fma2(unsigned long long a,
        unsigned long long b, unsigned long long c){
    unsigned long long d;
    asm("fma.rn.f32x2 %0,%1,%2,%3;" : "=l"(d) : "l"(a), "l"(b), "l"(c));
    return d;
}

__device__ __forceinline__ float peps_el(const float* __restrict__ peps,
                                         int i,int j,int p,int u,int d,int l,int r){
    return peps[(((((i*5+j)*2+p)*4+u)*4+d)*4+l)*4+r];
}

// ---- software grid barrier (all GRID blocks co-resident: 1 block/SM) ----
__device__ __forceinline__ void gridbar(){
    __syncthreads();
    if (threadIdx.x==0){
        __threadfence();
        unsigned gen = atomicAdd(&g_gen, 0u);
        if (atomicAdd(&g_bar, 1u) == GRID-1u){
            atomicExch(&g_bar, 0u);
            atomicAdd(&g_gen, 1u);
        } else {
            while (atomicAdd(&g_gen, 0u) == gen) __nanosleep(64);
        }
        __threadfence();
    }
    __syncthreads();
}

__global__ __launch_bounds__(256)
void mega_kernel(const int* __restrict__ x, const float* __restrict__ peps,
                 const float* __restrict__ gate, float* __restrict__ out){
    __shared__ __align__(16) float SM[10600];   // 42.4 KB arena
    const int tid = threadIdx.x;
    const int blk = blockIdx.x;

    // ================= phase 1: prep (11 tasks: 10 K_j + 1 RC build) =================
    for (int task = blk; task < 11; task += GRID){
        __syncthreads();
        if (task < 10){
            int pair = task/5, j = task%5;
            int L = (j==0)?1:4, R = (j==4)?1:4;
            int nk = 16*L*L*R*R;
            float* Kg = g_K + task*4096;
            for (int e=tid; e<nk; e+=256){
                int tt=e;
                int rb=tt%R; tt/=R; int ra=tt%R; tt/=R;
                int lb=tt%L; tt/=L; int la=tt%L; tt/=L;
                int mid=tt&3; tt>>=2;
                int pb=tt&1; int pa=tt>>1;
                float s=0.f;
                if (pair==0){
                    #pragma unroll
                    for(int m=0;m<4;m++)
                        s += peps_el(peps,0,j,pa,0,m,la,ra)*peps_el(peps,1,j,pb,m,mid,lb,rb);
                } else {
                    #pragma unroll
                    for(int m=0;m<4;m++)
                        s += peps_el(peps,2,j,pa,mid,m,la,ra)*peps_el(peps,3,j,pb,m,0,lb,rb);
                }
                __stcg(&Kg[e], s);
            }
        } else {
            float* g  = SM;          // 16
            float* A0 = SM+16;       // 1024
            float* A1 = SM+1040;     // 1024
            if (tid<16) g[tid]=gate[tid];
            for (int e=tid;e<1024;e+=256) A0[e] = ((e>>5)==(e&31)) ? 1.0f : 0.0f;
            __syncthreads();
            #pragma unroll
            for (int k=0;k<4;k++){
                const float* cur = (k&1)? A1 : A0;
                float* nxt       = (k&1)? A0 : A1;
                int hb=4-k, lb=3-k;
                for (int e=tid;e<1024;e+=256){
                    int rp=e>>5, c=e&31;
                    int i1p=(rp>>hb)&1, i2p=(rp>>lb)&1;
                    int base = rp & ~((1<<hb)|(1<<lb));
                    float acc=0.f;
                    #pragma unroll
                    for(int i1=0;i1<2;i1++)
                    #pragma unroll
                    for(int i2=0;i2<2;i2++)
                        acc += g[(i1p*2+i2p)*4+(i1*2+i2)] * cur[(base|(i1<<hb)|(i2<<lb))*32 + c];
                    nxt[e]=acc;
                }
                __syncthreads();
            }
            for (int e=tid;e<1024;e+=256) __stcg(&g_R[e], A0[e]);
            __syncthreads();
            A0[tid] = ((tid>>4)==(tid&15)) ? 1.0f : 0.0f;
            __syncthreads();
            #pragma unroll
            for (int k=0;k<3;k++){
                const float* cur=(k&1)?A1:A0;
                float* nxt      =(k&1)?A0:A1;
                int hb=3-k, lb=2-k;
                int rp=tid>>4, c=tid&15;
                int i1p=(rp>>hb)&1,i2p=(rp>>lb)&1;
                int base = rp & ~((1<<hb)|(1<<lb));
                float acc=0.f;
                #pragma unroll
                for(int i1=0;i1<2;i1++)
                #pragma unroll
                for(int i2=0;i2<2;i2++)
                    acc += g[(i1p*2+i2p)*4+(i1*2+i2)]*cur[(base|(i1<<hb)|(i2<<lb))*16+c];
                __syncthreads();
                nxt[tid]=acc;
                __syncthreads();
            }
            __stcg(&g_C16[tid], A1[tid]);
        }
    }
    gridbar();

    // ================= phase 2: kkprep (512 slice tasks + 2 T2 tasks) =================
    for (int task = blk; task < 514; task += GRID){
        __syncthreads();
        if (task < 512){
            int pair = task>>8, pb = task&255;
            const float* Kbase = g_K + pair*5*4096;
            int pd = pb&15, pbb = (pb>>4)&3, pa = pb>>6;
            int kb2 = ((pa>>1)*2+(pbb>>1))*4+(pd>>2);
            int kb3 = ((pa&1)*2+(pbb&1))*4+(pd&3);
            float* K2s = SM;        // 256
            float* K3s = SM+256;    // 256
            K2s[tid] = __ldcg(&Kbase[2*4096 + kb2*256 + tid]);
            K3s[tid] = __ldcg(&Kbase[3*4096 + kb3*256 + tid]);
            __syncthreads();
            int l = tid>>4, r = tid&15;
            float acc=0.f;
            #pragma unroll
            for (int m=0;m<16;m++) acc += K2s[l*16+m]*K3s[m*16+r];
            __stcg(&g_KK[pair*65536 + pb*256 + tid], acc);
        } else {
            int pair = task-512;
            const float* Kbase = g_K + pair*5*4096;
            float* K0s = SM;        // 256
            float* K1s = SM+256;    // 4096
            K0s[tid]=__ldcg(&Kbase[tid]);
            for (int e=tid;e<4096;e+=256) K1s[e]=__ldcg(&Kbase[4096+e]);
            __syncthreads();
            int abc = tid;
            int a2=abc>>6, b2=(abc>>4)&3, c2=abc&15;
            int kb0 = ((a2>>1)*2+(b2>>1))*4 + (c2>>2);
            int kb1 = ((a2&1)*2+(b2&1))*4 + (c2&3);
            float* T2 = g_A + pair*4096;
            #pragma unroll
            for (int r=0;r<16;r++){
                float acc=0.f;
                #pragma unroll
                for (int m=0;m<16;m++) acc += K0s[kb0*16+m]*K1s[(kb1*16+m)*16+r];
                __stcg(&T2[abc*16+r], acc);
            }
        }
    }
    gridbar();

    // ================= phase 3: fold23 (512 tasks) =================
    for (int task = blk; task < 512; task += GRID){
        __syncthreads();
        int pair = task>>8, pb = task&255;
        int pd = pb&15, pbb = (pb>>4)&3, pa = pb>>6;
        float* Ts = SM;         // 5120 (256 rows pitch 20)
        float* Ks = SM+5120;    // 256
        const float* T2 = g_A + pair*4096;
        for (int e=tid;e<4096;e+=256) Ts[(e>>4)*20 + (e&15)] = __ldcg(&T2[e]);
        Ks[tid] = __ldcg(&g_KK[pair*65536 + pb*256 + tid]);
        __syncthreads();
        float* Tout = pair? g_T1 : g_T0;
        int a2=tid>>6, b2=(tid>>4)&3, c2=tid&15;
        float tv[16];
        #pragma unroll
        for (int l=0;l<16;l++) tv[l]=Ts[tid*20+l];
        long obase = ((((long)(a2*4+pa)*16 + b2*4+pbb)*256) + c2*16+pd)*16;
        #pragma unroll
        for (int r4=0;r4<4;r4++){
            float4 o; float* po=(float*)&o;
            #pragma unroll
            for (int q=0;q<4;q++){
                int r=r4*4+q;
                float acc=0.f;
                #pragma unroll
                for (int l=0;l<16;l++) acc += tv[l]*Ks[l*16+r];
                po[q]=acc;
            }
            __stcg((float4*)&Tout[obase + r4*4], o);
        }
    }
    gridbar();

    // ================= phase 4: fold4 (512 tasks) =================
    for (int task = blk; task < 512; task += GRID){
        __syncthreads();
        int pair = task>>8;
        int idx = task&255;
        int a = idx>>4, b = idx&15;
        int c = tid;
        float* K4s = SM;        // 256
        K4s[c] = __ldcg(&g_K[(pair*5+4)*4096 + c]);
        __syncthreads();
        const float* Tin = pair? g_T1 : g_T0;
        const float* tp = &Tin[(((long)(a*16+b)*256)+c)*16];
        float tv[16];
        #pragma unroll
        for (int l4=0;l4<4;l4++){
            float4 v = __ldcg((const float4*)&tp[l4*4]);
            tv[l4*4+0]=v.x; tv[l4*4+1]=v.y; tv[l4*4+2]=v.z; tv[l4*4+3]=v.w;
        }
        if (pair==0){
            long base = (long)a*65536 + (long)b*2048 + c*4;
            #pragma unroll
            for (int p0=0;p0<2;p0++)
            #pragma unroll
            for (int p1=0;p1<2;p1++){
                float4 o; float* po=(float*)&o;
                #pragma unroll
                for (int d1=0;d1<4;d1++){
                    int kb=(p0*2+p1)*4+d1;
                    float acc=0.f;
                    #pragma unroll
                    for (int l=0;l<16;l++) acc += tv[l]*K4s[kb*16+l];
                    po[d1]=acc;
                }
                __stcg((float4*)&g_A[base + p0*32768 + p1*1024], o);
            }
        } else {
            #pragma unroll
            for (int p0=0;p0<2;p0++)
            #pragma unroll
            for (int p1=0;p1<2;p1++){
                float4 o; float* po=(float*)&o;
                #pragma unroll
                for (int d1=0;d1<4;d1++){
                    int kb=(p0*2+p1)*4+d1;
                    float acc=0.f;
                    #pragma unroll
                    for (int l=0;l<16;l++) acc += tv[l]*K4s[kb*16+l];
                    po[d1]=acc;
                }
                long col = (long)(a*64 + p0*32 + b*2 + p1);
                __stcg((float4*)&g_Cm[col*1024 + c*4], o);
            }
        }
    }
    gridbar();

    // ================= phase 5: sgemm psi = A @ Ct^T (256 tile tasks) =================
    for (int task = blk; task < 256; task += GRID){
        __syncthreads();
        int bx = task&15, by = task>>4;
        float* As2 = SM;        // 16 x 132
        float* Bs  = SM+2112;   // 16 x 68
        int tx=tid&15, ty=tid>>4;
        unsigned long long acc2[4][2];
        #pragma unroll
        for(int i=0;i<4;i++){ acc2[i][0]=0ull; acc2[i][1]=0ull; }
        const float* Ablk  = g_A  + (long)(by*64)*1024;
        const float* Btblk = g_Cm + (long)(bx*64)*1024;
        for (int k0=0;k0<1024;k0+=16){
            #pragma unroll
            for (int e=0;e<4;e++){
                int idx = tid + e*256;
                int m = idx>>4, k = idx&15;
                float v = __ldcg(&Ablk[(long)m*1024 + k0 + k]);
                *(float2*)&As2[k*132 + 2*m] = make_float2(v,v);
            }
            #pragma unroll
            for (int e=0;e<4;e++){
                int idx = tid + e*256;
                int n = idx>>4, k = idx&15;
                Bs[k*68 + n] = __ldcg(&Btblk[(long)n*1024 + k0 + k]);
            }
            __syncthreads();
            #pragma unroll
            for (int k=0;k<16;k++){
                ulonglong2 a01 = *(const ulonglong2*)&As2[k*132 + ty*8];
                ulonglong2 a23 = *(const ulonglong2*)&As2[k*132 + ty*8+4];
                ulonglong2 bb  = *(const ulonglong2*)&Bs[k*68 + tx*4];
                acc2[0][0]=fma2(a01.x, bb.x, acc2[0][0]); acc2[0][1]=fma2(a01.x, bb.y, acc2[0][1]);
                acc2[1][0]=fma2(a01.y, bb.x, acc2[1][0]); acc2[1][1]=fma2(a01.y, bb.y, acc2[1][1]);
                acc2[2][0]=fma2(a23.x, bb.x, acc2[2][0]); acc2[2][1]=fma2(a23.x, bb.y, acc2[2][1]);
                acc2[3][0]=fma2(a23.y, bb.x, acc2[3][0]); acc2[3][1]=fma2(a23.y, bb.y, acc2[3][1]);
            }
            __syncthreads();
        }
        #pragma unroll
        for(int i=0;i<4;i++){
            float2 c0 = upk2(acc2[i][0]);
            float2 c1 = upk2(acc2[i][1]);
            float4 o = make_float4(c0.x, c0.y, c1.x, c1.y);
            __stcg((float4*)&g_psi[(long)(by*64+ty*4+i)*1024 + bx*64+tx*4], o);
        }
    }
    gridbar();

    // ================= phases 6..25: 5 sweeps x 4 layers, in-place on g_psi =================
    float* psi = g_psi;
    for (int sweep=0; sweep<5; sweep++){
        // ---- hhigh: bits [15-19] and [10-14] (128 tasks) ----
        {
            float* S   = SM;        // 8 x 1036
            float* Rs  = SM+8288;   // 1024
            float* RsT = SM+9312;   // 1024
            for (int e=tid;e<1024;e+=256){
                float v = __ldcg(&g_R[e]);
                Rs[e]=v;
                RsT[(e&31)*32 + (e>>5)] = v;
            }
            __syncthreads();
            for (int task = blk; task < 128; task += GRID){
                __syncthreads();
                unsigned lowbase = task * 8u;
                for (int it=0; it<32; it++){
                    int idx = tid + it*256;
                    int lo = idx & 7, k = idx >> 3;
                    S[lo*1036 + k] = __ldcg(&psi[(unsigned)k*1024u + lowbase + (unsigned)lo]);
                }
                __syncthreads();
                int low = tid & 7, rp = tid >> 3;
                unsigned long long U2[16];
                #pragma unroll
                for (int e=0;e<16;e++) U2[e]=0ull;
                for (int r=0;r<32;r++){
                    float rv = RsT[r*32+rp];
                    unsigned long long rvp = pk2(rv, rv);
                    const ulonglong2* row2 = (const ulonglong2*)&S[low*1036 + r*32];
                    #pragma unroll
                    for (int c2=0;c2<8;c2++){
                        ulonglong2 tp = row2[c2];
                        U2[c2*2+0] = fma2(rvp, tp.x, U2[c2*2+0]);
                        U2[c2*2+1] = fma2(rvp, tp.y, U2[c2*2+1]);
                    }
                }
                float W[32];
                #pragma unroll
                for (int cp=0;cp<32;cp++){
                    const ulonglong2* Rp2 = (const ulonglong2*)&Rs[cp*32];
                    unsigned long long s2 = 0ull;
                    #pragma unroll
                    for (int c2=0;c2<8;c2++){
                        ulonglong2 rr = Rp2[c2];
                        s2 = fma2(rr.x, U2[c2*2+0], s2);
                        s2 = fma2(rr.y, U2[c2*2+1], s2);
                    }
                    float2 f = upk2(s2);
                    W[cp] = f.x + f.y;
                }
                __syncthreads();
                #pragma unroll
                for (int cp=0;cp<32;cp++) S[low*1036 + rp*32+cp] = W[cp];
                __syncthreads();
                for (int it=0; it<32; it++){
                    int idx = tid + it*256;
                    int lo = idx & 7, k = idx >> 3;
                    __stcg(&psi[(unsigned)k*1024u + lowbase + (unsigned)lo], S[lo*1036 + k]);
                }
            }
        }
        gridbar();

        // ---- hlow: bits [5-9] and [0-4] (1024 tasks) ----
        {
            float* T   = SM;        // 32 x 33
            float* Usm = SM+1056;   // 32 x 33
            float* Rs  = SM+2112;   // 1024
            float* RsT = SM+3136;   // 1024
            for (int e=tid;e<1024;e+=256){
                float v = __ldcg(&g_R[e]);
                Rs[e]=v;
                RsT[(e&31)*32 + (e>>5)] = v;
            }
            __syncthreads();
            for (int task = blk; task < 1024; task += GRID){
                __syncthreads();
                unsigned base = task*1024u;
                #pragma unroll
                for (int it=0;it<4;it++){
                    int e = tid + it*256;
                    T[(e>>5)*33 + (e&31)] = __ldcg(&psi[base+e]);
                }
                __syncthreads();
                int rp = tid & 31, cq = tid >> 5;
                float u[4]={0.f,0.f,0.f,0.f};
                for (int r=0;r<32;r++){
                    float rv = RsT[r*32+rp];
                    #pragma unroll
                    for (int i=0;i<4;i++) u[i] += rv * T[r*33 + cq*4+i];
                }
                #pragma unroll
                for (int i=0;i<4;i++) Usm[rp*33 + cq*4+i]=u[i];
                __syncthreads();
                float w[4];
                #pragma unroll
                for (int i=0;i<4;i++){
                    int cp = cq*4+i;
                    float acc=0.f;
                    #pragma unroll
                    for (int c=0;c<32;c++) acc += Rs[cp*32+c]*Usm[rp*33 + c];
                    w[i]=acc;
                }
                __syncthreads();
                #pragma unroll
                for (int i=0;i<4;i++) T[rp*33 + cq*4+i]=w[i];
                __syncthreads();
                #pragma unroll
                for (int it=0;it<4;it++){
                    int e = tid + it*256;
                    __stcg(&psi[base+e], T[(e>>5)*33 + (e&31)]);
                }
            }
        }
        gridbar();

        // ---- v3: columns p=2,3,4 (256 tasks) ----
        {
            float* Cs = SM;        // 256
            float* S  = SM+256;    // 256*17 + 16
            Cs[tid]=__ldcg(&g_C16[tid]);
            __syncthreads();
            for (int task = blk; task < 256; task += GRID){
                __syncthreads();
                unsigned f = (unsigned)task;  // 8 bits
                unsigned tt=f;
                tt = ((tt>>2)<<5)   | (tt & 3u);
                tt = ((tt>>7)<<10)  | (tt & 127u);
                tt = ((tt>>12)<<15) | (tt & 4095u);
                tt = ((tt>>17)<<20) | (tt & 131071u);
                unsigned base=tt;
                {
                    int b=tid>>4, c=tid&15;
                    unsigned offb = ((unsigned)(b&1)<<3)|((unsigned)((b>>1)&1)<<8)|((unsigned)((b>>2)&1)<<13)|((unsigned)((b>>3)&1)<<18);
                    unsigned offc = ((unsigned)(c&1)<<4)|((unsigned)((c>>1)&1)<<9)|((unsigned)((c>>2)&1)<<14)|((unsigned)((c>>3)&1)<<19);
                    unsigned bs = base + offb + offc;
                    #pragma unroll
                    for (int a=0;a<16;a++){
                        unsigned offa = ((unsigned)(a&1)<<2)|((unsigned)((a>>1)&1)<<7)|((unsigned)((a>>2)&1)<<12)|((unsigned)((a>>3)&1)<<17);
                        S[tid*17 + a] = __ldcg(&psi[bs + offa]);
                    }
                }
                __syncthreads();
                {
                    float v[16], o[16];
                    #pragma unroll
                    for (int a=0;a<16;a++) v[a]=S[tid*17+a];
                    #pragma unroll
                    for (int ap=0;ap<16;ap++){
                        float acc=0.f;
                        #pragma unroll
                        for (int a=0;a<16;a++) acc += Cs[ap*16+a]*v[a];
                        o[ap]=acc;
                    }
                    #pragma unroll
                    for (int a=0;a<16;a++) S[tid*17+a]=o[a];
                }
                __syncthreads();
                {
                    int a=tid>>4, c=tid&15;
                    float v[16], o[16];
                    #pragma unroll
                    for (int b=0;b<16;b++) v[b]=S[(b*16+c)*17 + a];
                    #pragma unroll
                    for (int bp=0;bp<16;bp++){
                        float acc=0.f;
                        #pragma unroll
                        for (int b=0;b<16;b++) acc += Cs[bp*16+b]*v[b];
                        o[bp]=acc;
                    }
                    #pragma unroll
                    for (int b=0;b<16;b++) S[(b*16+c)*17 + a]=o[b];
                }
                __syncthreads();
                {
                    int a=tid&15, b=tid>>4;
                    float v[16], o[16];
                    #pragma unroll
                    for (int c=0;c<16;c++) v[c]=S[(b*16+c)*17 + a];
                    #pragma unroll
                    for (int cp=0;cp<16;cp++){
                        float acc=0.f;
                        #pragma unroll
                        for (int c=0;c<16;c++) acc += Cs[cp*16+c]*v[c];
                        o[cp]=acc;
                    }
                    #pragma unroll
                    for (int c=0;c<16;c++) S[(b*16+c)*17 + a]=o[c];
                }
                __syncthreads();
                {
                    int b=tid>>4, c=tid&15;
                    unsigned offb = ((unsigned)(b&1)<<3)|((unsigned)((b>>1)&1)<<8)|((unsigned)((b>>2)&1)<<13)|((unsigned)((b>>3)&1)<<18);
                    unsigned offc = ((unsigned)(c&1)<<4)|((unsigned)((c>>1)&1)<<9)|((unsigned)((c>>2)&1)<<14)|((unsigned)((c>>3)&1)<<19);
                    unsigned bs = base + offb + offc;
                    #pragma unroll
                    for (int a=0;a<16;a++){
                        unsigned offa = ((unsigned)(a&1)<<2)|((unsigned)((a>>1)&1)<<7)|((unsigned)((a>>2)&1)<<12)|((unsigned)((a>>3)&1)<<17);
                        __stcg(&psi[bs + offa], S[tid*17 + a]);
                    }
                }
            }
        }
        gridbar();

        // ---- v2: columns p=0,1 (512 tasks, warp-private slabs) ----
        {
            const int p = 0;
            float* Cs  = SM;       // 256
            float* Tsm = SM+256;   // 8*16*17
            float* Usm = SM+2432;  // 8*16*17
            Cs[tid]=__ldcg(&g_C16[tid]);
            __syncthreads();
            int w = tid>>5, l = tid&31;
            for (int task = blk; task < 512; task += GRID){
                unsigned f = (unsigned)task*8u + (unsigned)w;
                unsigned tt=f;
                tt = ((tt>>p)<<(p+2))        | (tt & ((1u<<p)-1u));
                tt = ((tt>>(p+5))<<(p+7))    | (tt & ((1u<<(p+5))-1u));
                tt = ((tt>>(p+10))<<(p+12))  | (tt & ((1u<<(p+10))-1u));
                tt = ((tt>>(p+15))<<(p+17))  | (tt & ((1u<<(p+15))-1u));
                unsigned base=tt;
                unsigned offs[8];
                #pragma unroll
                for (int t=0;t<8;t++){
                    int e = l + 32*t;
                    int i0 = e & 15, i1 = e >> 4;
                    unsigned off =
                        (unsigned)(((i0&1)|((i1&1)<<1)) << p) |
                        (unsigned)((((i0>>1)&1)|(((i1>>1)&1)<<1)) << (p+5)) |
                        (unsigned)((((i0>>2)&1)|(((i1>>2)&1)<<1)) << (p+10)) |
                        (unsigned)((((i0>>3)&1)|(((i1>>3)&1)<<1)) << (p+15));
                    offs[t]=off;
                    Tsm[(w*16+i1)*17 + i0] = __ldcg(&psi[base+off]);
                }
                __syncwarp();
                #pragma unroll
                for (int t=0;t<8;t++){
                    int e = l + 32*t;
                    int c = e & 15, o = e >> 4;
                    float acc=0.f;
                    #pragma unroll
                    for (int k=0;k<16;k++) acc += Cs[o*16+k]*Tsm[(w*16+k)*17 + c];
                    Usm[(w*16+o)*17 + c]=acc;
                }
                __syncwarp();
                #pragma unroll
                for (int t=0;t<8;t++){
                    int e = l + 32*t;
                    int i0 = e & 15, i1 = e >> 4;
                    float acc=0.f;
                    #pragma unroll
                    for (int c=0;c<16;c++) acc += Cs[i0*16+c]*Usm[(w*16+i1)*17 + c];
                    __stcg(&psi[base+offs[t]], acc);
                }
                __syncwarp();
            }
        }
        gridbar();
    }

    // ================= final: gather 64 amplitudes =================
    if (blk==0 && tid<64){
        unsigned idx=0;
        #pragma unroll
        for (int j=0;j<20;j++) idx = (idx<<1) | (unsigned)x[tid*20+j];
        __stcg(&out[tid], __ldcg(&psi[idx]));
    }
}

extern "C" void kernel_launch(void* const* d_in, const int* in_sizes, int n_in,
                              void* d_out, int out_size){
    const int*   x    = (const int*)d_in[0];
    const float* peps = (const float*)d_in[1];
    const float* gate = (const float*)d_in[2];
    float* out = (float*)d_out;
    mega_kernel<<<GRID,256>>>(x, peps, gate, out);
}